// round 16
// baseline (speedup 1.0000x reference)
#include <cuda_runtime.h>
#include <cuda_bf16.h>
#include <cuda_fp16.h>
#include <cstdint>

// ---------------------------------------------------------------------------
// LightweightSelfAttention  (B=2, C=512, H=W=64, heads=8, dh=64)
// All-tcgen05, fp16 data plane.
// R16: GEMM single-buffer (49KB) -> occ 4; chunked epilogue kept (regs ~85).
//      Cross-CTA overlap replaces intra-CTA double buffering (R15 was neutral:
//      latency-bound at occ 1-2). Attention unchanged from R14.
// ---------------------------------------------------------------------------

#if defined(__CUDA_ARCH_FEAT_SM103_ALL) || defined(__CUDA_ARCH_FEAT_SM100_ALL)
#define HAS_TC 1
#else
#define HAS_TC 0
#endif

#define BATCH 2
#define CDIM 512
#define HEADS 8
#define DH 64
#define NPIX 4096
#define TOTAL (BATCH*CDIM*NPIX)
#define QKD 1024

typedef unsigned short u16;
typedef unsigned long long u64;

__device__ u16 g_ythi[BATCH * NPIX * CDIM];
__device__ u16 g_ytlo[BATCH * NPIX * CDIM];
__device__ u16 g_whi[3 * CDIM * CDIM];
__device__ u16 g_wlo[3 * CDIM * CDIM];
__device__ u16 g_pwhi[CDIM * CDIM];
__device__ u16 g_pwlo[CDIM * CDIM];
__device__ u16 g_qkthi[BATCH * NPIX * QKD];
__device__ u16 g_qktlo[BATCH * NPIX * QKD];
__device__ u16 g_vth[BATCH * CDIM * NPIX];
__device__ u16 g_oth[BATCH * NPIX * CDIM];

#define ATT_SCALE_L2E 0.18033688f

// ---------------- helpers --------------------------------------------------
__device__ __forceinline__ uint32_t smem_u32(const void* p) {
    uint32_t a;
    asm("{ .reg .u64 t; cvta.to.shared.u64 t, %1; cvt.u32.u64 %0, t; }"
        : "=r"(a) : "l"(p));
    return a;
}
__device__ __forceinline__ u16 f2h(float x) {
    return __half_as_ushort(__float2half_rn(x));
}
__device__ __forceinline__ float h2f(u16 u) {
    return __half2float(__ushort_as_half(u));
}
#define SWZ(o) ((o) ^ (((o) >> 3) & 0x70))

#if HAS_TC
__device__ __forceinline__ unsigned elect1() {
    unsigned p;
    asm volatile("{\n\t.reg .pred p;\n\telect.sync _|p, 0xFFFFFFFF;\n\t"
                 "selp.b32 %0, 1, 0, p;\n\t}" : "=r"(p));
    return p;
}
__device__ __forceinline__ void mma_ss(uint32_t d, u64 a, u64 b, uint32_t id, uint32_t en) {
    asm volatile("{\n\t.reg .pred p;\n\tsetp.ne.u32 p, %5, 0;\n\t"
        "tcgen05.mma.cta_group::1.kind::f16 [%0], %1, %2, %3, {%4,%4,%4,%4}, p;\n\t}"
        :: "r"(d), "l"(a), "l"(b), "r"(id), "r"(0u), "r"(en) : "memory");
}
__device__ __forceinline__ void mma_ts(uint32_t d, uint32_t a, u64 b, uint32_t id, uint32_t en) {
    asm volatile("{\n\t.reg .pred p;\n\tsetp.ne.u32 p, %5, 0;\n\t"
        "tcgen05.mma.cta_group::1.kind::f16 [%0], [%1], %2, %3, {%4,%4,%4,%4}, p;\n\t}"
        :: "r"(d), "r"(a), "l"(b), "r"(id), "r"(0u), "r"(en) : "memory");
}
__device__ __forceinline__ void tc_commit(uint32_t mbar) {
    asm volatile("tcgen05.commit.cta_group::1.mbarrier::arrive::one.shared::cluster.b64 [%0];"
                 :: "r"(mbar) : "memory");
}
__device__ __forceinline__ void mbar_init1(uint32_t mbar) {
    asm volatile("mbarrier.init.shared.b64 [%0], %1;" :: "r"(mbar), "r"(1u) : "memory");
}
__device__ __forceinline__ void mbar_wait(uint32_t mbar, uint32_t ph) {
    asm volatile("{\n\t.reg .pred P1;\n\tLAB1_%=:\n\t"
        "mbarrier.try_wait.parity.acquire.cta.shared::cta.b64 P1, [%0], %1, 0x989680;\n\t"
        "@P1 bra.uni LAB2_%=;\n\tbra.uni LAB1_%=;\n\tLAB2_%=:\n\t}"
        :: "r"(mbar), "r"(ph) : "memory");
}
#define TCF_AFTER()  asm volatile("tcgen05.fence::after_thread_sync;" ::: "memory")
#define TCF_BEFORE() asm volatile("tcgen05.fence::before_thread_sync;" ::: "memory")
#define FPROXY()     asm volatile("fence.proxy.async.shared::cta;" ::: "memory")
#define TC_WAIT_LD() asm volatile("tcgen05.wait::ld.sync.aligned;" ::: "memory")
#define TC_WAIT_ST() asm volatile("tcgen05.wait::st.sync.aligned;" ::: "memory")

#define LDX32(r, ta) \
    asm volatile("tcgen05.ld.sync.aligned.32x32b.x32.b32 " \
        "{%0, %1, %2, %3, %4, %5, %6, %7, %8, %9, %10, %11, %12, %13, %14, %15, " \
        " %16, %17, %18, %19, %20, %21, %22, %23, %24, %25, %26, %27, %28, %29, %30, %31}, [%32];" \
        : "=r"((r)[0]),  "=r"((r)[1]),  "=r"((r)[2]),  "=r"((r)[3]), \
          "=r"((r)[4]),  "=r"((r)[5]),  "=r"((r)[6]),  "=r"((r)[7]), \
          "=r"((r)[8]),  "=r"((r)[9]),  "=r"((r)[10]), "=r"((r)[11]), \
          "=r"((r)[12]), "=r"((r)[13]), "=r"((r)[14]), "=r"((r)[15]), \
          "=r"((r)[16]), "=r"((r)[17]), "=r"((r)[18]), "=r"((r)[19]), \
          "=r"((r)[20]), "=r"((r)[21]), "=r"((r)[22]), "=r"((r)[23]), \
          "=r"((r)[24]), "=r"((r)[25]), "=r"((r)[26]), "=r"((r)[27]), \
          "=r"((r)[28]), "=r"((r)[29]), "=r"((r)[30]), "=r"((r)[31]) \
        : "r"(ta))

#define STX16(ta, r) \
    asm volatile("tcgen05.st.sync.aligned.32x32b.x16.b32 [%0], " \
        "{%1, %2, %3, %4, %5, %6, %7, %8, %9, %10, %11, %12, %13, %14, %15, %16};" \
        :: "r"(ta), \
           "r"((r)[0]),  "r"((r)[1]),  "r"((r)[2]),  "r"((r)[3]), \
           "r"((r)[4]),  "r"((r)[5]),  "r"((r)[6]),  "r"((r)[7]), \
           "r"((r)[8]),  "r"((r)[9]),  "r"((r)[10]), "r"((r)[11]), \
           "r"((r)[12]), "r"((r)[13]), "r"((r)[14]), "r"((r)[15]) \
        : "memory")

#define DESC_K  ((2ull<<61)|(1ull<<46)|(64ull<<32)|(1ull<<16))
__device__ __forceinline__ u64 mkdesc(uint32_t addr) {
    return DESC_K | ((u64)(addr >> 4) & 0x3FFF);
}
#define IDESC64H   ((1u<<4)|(8u<<17)|(8u<<24))
#define IDESC128H  ((1u<<4)|(16u<<17)|(8u<<24))
#endif  // HAS_TC

// ---------------- 1) fused dwconv + transpose + fp16 split -----------------
__global__ void k_dwt(const float* __restrict__ x, const float* __restrict__ w,
                      u16* __restrict__ thi, u16* __restrict__ tlo) {
    __shared__ float t[32][33];
    int b = blockIdx.z;
    int c0 = blockIdx.y * 32, n0 = blockIdx.x * 32;
    int hh = n0 >> 6, w0 = n0 & 63;
    int tx = threadIdx.x, ty = threadIdx.y;
#pragma unroll
    for (int j = 0; j < 4; j++) {
        int c = c0 + ty + j * 8;
        const float* xb = x + ((long long)(b * CDIM + c)) * NPIX;
        const float* wc = w + c * 9;
        int ww = w0 + tx;
        float s = 0.f;
#pragma unroll
        for (int i = 0; i < 3; i++) {
            int h2 = hh + i - 1;
            if ((unsigned)h2 < 64u) {
#pragma unroll
                for (int jj = 0; jj < 3; jj++) {
                    int w2 = ww + jj - 1;
                    if ((unsigned)w2 < 64u) s += xb[h2 * 64 + w2] * wc[i * 3 + jj];
                }
            }
        }
        t[ty + j * 8][tx] = s;
    }
    __syncthreads();
    long long zt = (long long)b * NPIX * CDIM;
#pragma unroll
    for (int j = 0; j < 4; j++) {
        int n = n0 + ty + j * 8;
        float v = t[tx][ty + j * 8];
        u16 h = f2h(v);
        thi[zt + (long long)n * CDIM + c0 + tx] = h;
        tlo[zt + (long long)n * CDIM + c0 + tx] = f2h(v - h2f(h));
    }
}

// ---------------- 2) fp32 -> fp16 hi/lo (weights) --------------------------
__global__ void k_cvt(const float* __restrict__ src, u16* __restrict__ hi,
                      u16* __restrict__ lo, int n) {
    int i = blockIdx.x * blockDim.x + threadIdx.x;
    if (i >= n) return;
    float v = src[i];
    u16 h = f2h(v);
    hi[i] = h;
    lo[i] = f2h(v - h2f(h));
}

// ---------------- 4/5/7) tcgen05 GEMM: 128x128, single buffer, occ 4 -------
#define GM_TMEMPTR 0
#define GM_MBAR 8
#define GM_AHI 1024
#define GM_ALO (GM_AHI + 16384)
#define GM_B   (GM_ALO + 16384)
#define GM_SMEM (GM_B + 16384)

__global__ void __launch_bounds__(256, 4) k_gemm_tc(
    const uint4* __restrict__ Ahi, const uint4* __restrict__ Alo, long long sA,
    const uint4* __restrict__ B, long long sB,
    u16* __restrict__ Ohi, u16* __restrict__ Olo,
    float* __restrict__ Ofp, const float* __restrict__ bias,
    long long sO, int ldo, float scale_q, int qcols, int out_mode) {
#if HAS_TC
    extern __shared__ char sm[];
    uint32_t sb = smem_u32(sm);
    int tid = threadIdx.x, wid = tid >> 5;
    int mrow0 = blockIdx.x * 128;
    int brow0 = blockIdx.y * 128;
    const uint4* Ah = Ahi + blockIdx.z * sA + (long long)mrow0 * 64;
    const uint4* Al = Alo + blockIdx.z * sA + (long long)mrow0 * 64;
    const uint4* Bb = B + blockIdx.z * sB + (long long)brow0 * 64;

    if (wid == 0) {
        asm volatile("tcgen05.alloc.cta_group::1.sync.aligned.shared::cta.b32 [%0], %1;"
                     :: "r"(sb + GM_TMEMPTR), "r"(128u) : "memory");
    }
    if (tid == 0) mbar_init1(sb + GM_MBAR);
    __syncthreads();
    uint32_t tb;
    asm volatile("ld.shared.b32 %0, [%1];" : "=r"(tb) : "r"(sb + GM_TMEMPTR));

    u64 dAhi = mkdesc(sb + GM_AHI);
    u64 dAlo = mkdesc(sb + GM_ALO);
    u64 dB   = mkdesc(sb + GM_B);

    uint32_t ph = 0;
#pragma unroll 1
    for (int kc = 0; kc < 8; kc++) {
        if (kc) { mbar_wait(sb + GM_MBAR, ph); ph ^= 1; }
        int k8 = kc * 8;
#pragma unroll
        for (int l = 0; l < 4; l++) {
            int idx = tid + l * 256;
            int r = idx >> 3, j = idx & 7;
            uint32_t off = SWZ((uint32_t)(r * 128 + j * 16));
            *(uint4*)(sm + GM_AHI + off) = Ah[r * 64 + k8 + j];
            *(uint4*)(sm + GM_ALO + off) = Al[r * 64 + k8 + j];
            *(uint4*)(sm + GM_B + off)   = Bb[r * 64 + k8 + j];
        }
        FPROXY();
        __syncthreads();
        if (wid == 0) {
            if (elect1()) {
#pragma unroll
                for (int ks = 0; ks < 4; ks++)
                    mma_ss(tb, dAhi + ks * 2, dB + ks * 2, IDESC128H, !(kc == 0 && ks == 0));
#pragma unroll
                for (int ks = 0; ks < 4; ks++)
                    mma_ss(tb, dAlo + ks * 2, dB + ks * 2, IDESC128H, 1u);
                tc_commit(sb + GM_MBAR);
            }
        }
    }
    mbar_wait(sb + GM_MBAR, ph); ph ^= 1;

    if (tid < 128) {
        TCF_AFTER();
        int m = mrow0 + tid;
        long long obase0 = blockIdx.z * sO + (long long)m * ldo + brow0;
#pragma unroll 1
        for (int ch = 0; ch < 4; ch++) {
            uint32_t d[32];
            LDX32(d, tb + ch * 32);
            TC_WAIT_LD();
            long long obase = obase0 + ch * 32;
            if (Ofp) {
                float bv = bias ? bias[m] : 0.f;
#pragma unroll
                for (int j = 0; j < 8; j++) {
                    float4 v = make_float4(__uint_as_float(d[4 * j]) + bv,
                                           __uint_as_float(d[4 * j + 1]) + bv,
                                           __uint_as_float(d[4 * j + 2]) + bv,
                                           __uint_as_float(d[4 * j + 3]) + bv);
                    *(float4*)(Ofp + obase + 4 * j) = v;
                }
            } else if (out_mode == 2 && brow0 < qcols) {
                uint32_t whi[16], wlo[16];
#pragma unroll
                for (int j = 0; j < 16; j++) {
                    float a = __uint_as_float(d[2 * j]) * scale_q;
                    float c = __uint_as_float(d[2 * j + 1]) * scale_q;
                    u16 ah = f2h(a), chh = f2h(c);
                    whi[j] = (uint32_t)ah | ((uint32_t)chh << 16);
                    u16 al = f2h(a - h2f(ah)), cl = f2h(c - h2f(chh));
                    wlo[j] = (uint32_t)al | ((uint32_t)cl << 16);
                }
#pragma unroll
                for (int j = 0; j < 4; j++) {
                    *(uint4*)(Ohi + obase + 8 * j) = *(uint4*)&whi[4 * j];
                    *(uint4*)(Olo + obase + 8 * j) = *(uint4*)&wlo[4 * j];
                }
            } else {
                uint32_t w[16];
#pragma unroll
                for (int j = 0; j < 16; j++) {
                    u16 a = f2h(__uint_as_float(d[2 * j]));
                    u16 c = f2h(__uint_as_float(d[2 * j + 1]));
                    w[j] = (uint32_t)a | ((uint32_t)c << 16);
                }
#pragma unroll
                for (int j = 0; j < 4; j++)
                    *(uint4*)(Ohi + obase + 8 * j) = *(uint4*)&w[4 * j];
            }
        }
    }
    __syncthreads();
    if (wid == 0) {
        asm volatile("tcgen05.dealloc.cta_group::1.sync.aligned.b32 %0, %1;"
                     :: "r"(tb), "r"(128u));
    }
#else
    // compile-only fallback
    int tid = threadIdx.x;
    const u16* Ah = (const u16*)(Ahi + blockIdx.z * sA) + (long long)blockIdx.x * 128 * 512;
    const u16* Al = (const u16*)(Alo + blockIdx.z * sA) + (long long)blockIdx.x * 128 * 512;
    const u16* Bb = (const u16*)(B + blockIdx.z * sB) + (long long)blockIdx.y * 128 * 512;
    for (int e = tid; e < 128 * 128; e += 256) {
        int r = e >> 7, j = e & 127;
        float s = 0.f;
        for (int k = 0; k < 512; k++)
            s += (h2f(Ah[r * 512 + k]) + h2f(Al[r * 512 + k])) * h2f(Bb[j * 512 + k]);
        int m = blockIdx.x * 128 + r;
        long long obase = blockIdx.z * sO + (long long)m * ldo + blockIdx.y * 128 + j;
        if (Ofp) {
            Ofp[obase] = s + (bias ? bias[m] : 0.f);
        } else if (out_mode == 2 && blockIdx.y * 128 < qcols) {
            s *= scale_q;
            u16 hh = f2h(s);
            Ohi[obase] = hh;
            Olo[obase] = f2h(s - h2f(hh));
        } else {
            Ohi[obase] = f2h(s);
        }
    }
#endif
}

// ---------------- 6) attention (R14-exact) ---------------------------------
#define SM_TMEMPTR 0
#define SM_MBAR 8
#define SM_DEN 1024
#define SM_QHI 2048
#define SM_QLO (SM_QHI + 16384)
#define SM_KH(b) (34816 + (b) * 8192)
#define SM_VH(b) (51200 + (b) * 8192)
#define ATT_SMEM 67584

#define TM_S(b) ((b) * 64)
#define TM_O 128
#define TM_PH 192
#define ATT_TMCOLS 256

__global__ void __launch_bounds__(256) k_attn(
    const u16* __restrict__ qkthi, const u16* __restrict__ qktlo,
    const u16* __restrict__ vth, u16* __restrict__ oth) {
#if HAS_TC
    extern __shared__ char sm[];
    uint32_t sb = smem_u32(sm);
    int tid = threadIdx.x, wid = tid >> 5;
    int half = wid >> 2;
    uint32_t lofs = (uint32_t)(wid & 3) << 21;
    int n0 = blockIdx.x * 128;
    int h = blockIdx.y, b = blockIdx.z;
    const uint4* qh4 = (const uint4*)qkthi + (long long)b * NPIX * 128;
    const uint4* ql4 = (const uint4*)qktlo + (long long)b * NPIX * 128;
    const uint4* vh4 = (const uint4*)vth + ((long long)b * CDIM + h * DH) * 512;

    if (wid == 0) {
        asm volatile("tcgen05.alloc.cta_group::1.sync.aligned.shared::cta.b32 [%0], %1;"
                     :: "r"(sb + SM_TMEMPTR), "r"((uint32_t)ATT_TMCOLS) : "memory");
    }
    if (tid == 0) mbar_init1(sb + SM_MBAR);
    __syncthreads();
    uint32_t tb;
    asm volatile("ld.shared.b32 %0, [%1];" : "=r"(tb) : "r"(sb + SM_TMEMPTR));

    int r0a = tid >> 3, ja = tid & 7;
    int r0b = (tid + 256) >> 3, jb = (tid + 256) & 7;
    uint32_t offa = SWZ((uint32_t)(r0a * 128 + ja * 16));
    uint32_t offb = SWZ((uint32_t)(r0b * 128 + jb * 16));

#pragma unroll
    for (int l = 0; l < 4; l++) {
        int idx = tid + l * 256;
        int r = idx >> 3, j = idx & 7;
        uint32_t off = SWZ((uint32_t)(r * 128 + j * 16));
        *(uint4*)(sm + SM_QHI + off) = qh4[(long long)(n0 + r) * 128 + h * 8 + j];
        *(uint4*)(sm + SM_QLO + off) = ql4[(long long)(n0 + r) * 128 + h * 8 + j];
    }
#pragma unroll
    for (int l = 0; l < 2; l++) {
        int idx = tid + l * 256;
        int r = idx >> 3, j = idx & 7;
        uint32_t off = SWZ((uint32_t)(r * 128 + j * 16));
        *(uint4*)(sm + SM_KH(0) + off) = qh4[(long long)r * 128 + 64 + h * 8 + j];
        *(uint4*)(sm + SM_KH(1) + off) = qh4[(long long)(64 + r) * 128 + 64 + h * 8 + j];
        *(uint4*)(sm + SM_VH(0) + off) = vh4[(long long)r * 512 + j];
    }
    FPROXY();
    __syncthreads();

    u64 aQhi = mkdesc(sb + SM_QHI);
    u64 aQlo = mkdesc(sb + SM_QLO);

    if (wid == 0) {
        if (elect1()) {
            u64 dK = mkdesc(sb + SM_KH(0));
#pragma unroll
            for (int ks = 0; ks < 4; ks++)
                mma_ss(tb + TM_S(0), aQhi + ks * 2, dK + ks * 2, IDESC64H, ks > 0);
#pragma unroll
            for (int ks = 0; ks < 4; ks++)
                mma_ss(tb + TM_S(0), aQlo + ks * 2, dK + ks * 2, IDESC64H, 1u);
            tc_commit(sb + SM_MBAR);
        }
    }

    float den = 0.f;
    uint32_t ph = 0;

#pragma unroll 1
    for (int t = 0; t < 64; t++) {
        mbar_wait(sb + SM_MBAR, ph); ph ^= 1;
        TCF_AFTER();

        if (t < 63 && wid == 0) {
            if (elect1()) {
                int nb = (t + 1) & 1;
                u64 dK = mkdesc(sb + SM_KH(nb));
#pragma unroll
                for (int ks = 0; ks < 4; ks++)
                    mma_ss(tb + TM_S(nb), aQhi + ks * 2, dK + ks * 2, IDESC64H, ks > 0);
#pragma unroll
                for (int ks = 0; ks < 4; ks++)
                    mma_ss(tb + TM_S(nb), aQlo + ks * 2, dK + ks * 2, IDESC64H, 1u);
            }
        }

        uint4 kra, krb, vra, vrb;
        bool hask = (t <= 61), hasv = (t <= 62);
        if (hask) {
            int m2 = (t + 2) * 64;
            kra = qh4[(long long)(m2 + r0a) * 128 + 64 + h * 8 + ja];
            krb = qh4[(long long)(m2 + r0b) * 128 + 64 + h * 8 + jb];
        }
        if (hasv) {
            int m1 = (t + 1) * 8;
            vra = vh4[(long long)r0a * 512 + m1 + ja];
            vrb = vh4[(long long)r0b * 512 + m1 + jb];
        }

        {
            uint32_t sr[32];
            LDX32(sr, tb + TM_S(t & 1) + half * 32);
            TC_WAIT_LD();
            uint32_t w[16];
            float dsum = 0.f;
#pragma unroll
            for (int j = 0; j < 16; j++) {
                uint32_t s2, p2;
                asm("cvt.rn.f16x2.f32 %0, %1, %2;" : "=r"(s2)
                    : "f"(__uint_as_float(sr[2 * j + 1])), "f"(__uint_as_float(sr[2 * j])));
                asm("ex2.approx.f16x2 %0, %1;" : "=r"(p2) : "r"(s2));
                w[j] = p2;
                dsum += h2f((u16)(p2 & 0xFFFF)) + h2f((u16)(p2 >> 16));
            }
            den += dsum;
            STX16(tb + TM_PH + half * 16 + lofs, w);
            TC_WAIT_ST();
        }

        if (hask) {
            *(uint4*)(sm + SM_KH(t & 1) + offa) = kra;
            *(uint4*)(sm + SM_KH(t & 1) + offb) = krb;
        }
        if (hasv) {
            *(uint4*)(sm + SM_VH((t + 1) & 1) + offa) = vra;
            *(uint4*)(sm + SM_VH((t + 1) & 1) + offb) = vrb;
        }
        TCF_BEFORE();
        FPROXY();
        __syncthreads();

        if (wid == 0) {
            if (elect1()) {
                TCF_AFTER();
                u64 dVh = mkdesc(sb + SM_VH(t & 1));
#pragma unroll
                for (int ks = 0; ks < 4; ks++)
                    mma_ts(tb + TM_O, tb + TM_PH + ks * 8, dVh + ks * 2, IDESC64H,
                           (t > 0 || ks > 0) ? 1u : 0u);
                tc_commit(sb + SM_MBAR);
            }
        }
    }
    mbar_wait(sb + SM_MBAR, ph); ph ^= 1;

    *(float*)(sm + SM_DEN + tid * 4) = den;
    __syncthreads();

    if (tid < 128) {
        TCF_AFTER();
        uint32_t orr[64];
        LDX32(orr, tb + TM_O);
        LDX32(orr + 32, tb + TM_O + 32);
        TC_WAIT_LD();
        float dtot = *(float*)(sm + SM_DEN + tid * 4) +
                     *(float*)(sm + SM_DEN + (tid + 128) * 4);
        float inv = 1.0f / dtot;
        long long obase = ((long long)b * NPIX + n0 + tid) * CDIM + h * DH;
        uint32_t w[32];
#pragma unroll
        for (int j = 0; j < 32; j++) {
            u16 a = f2h(__uint_as_float(orr[2 * j]) * inv);
            u16 c = f2h(__uint_as_float(orr[2 * j + 1]) * inv);
            w[j] = (uint32_t)a | ((uint32_t)c << 16);
        }
#pragma unroll
        for (int j = 0; j < 8; j++)
            *(uint4*)(oth + obase + 8 * j) = *(uint4*)&w[4 * j];
    }
    __syncthreads();
    if (wid == 0) {
        asm volatile("tcgen05.dealloc.cta_group::1.sync.aligned.b32 %0, %1;"
                     :: "r"(tb), "r"((uint32_t)ATT_TMCOLS));
    }
#else
    // compile-only fallback
    int tid = threadIdx.x;
    if (tid >= 128) return;
    int n0 = blockIdx.x * 128;
    int h = blockIdx.y, b = blockIdx.z;
    long long qb = (long long)b * NPIX * QKD;
    int r = n0 + tid;
    float q[64], o[64], den = 0.f;
#pragma unroll
    for (int d = 0; d < 64; d++) {
        q[d] = h2f(qkthi[qb + (long long)r * QKD + h * 64 + d]) +
               h2f(qktlo[qb + (long long)r * QKD + h * 64 + d]);
        o[d] = 0.f;
    }
    for (int key = 0; key < NPIX; key++) {
        float s = 0.f;
        for (int d = 0; d < 64; d++)
            s += q[d] * h2f(qkthi[qb + (long long)key * QKD + 512 + h * 64 + d]);
        float p = h2f(f2h(exp2f(h2f(f2h(s)))));
        den += p;
        for (int d = 0; d < 64; d++) {
            long long vi = ((long long)b * CDIM + h * 64 + d) * NPIX + key;
            o[d] += p * h2f(vth[vi]);
        }
    }
    long long ob = ((long long)b * NPIX + r) * CDIM + h * 64;
    for (int d = 0; d < 64; d++) oth[ob + d] = f2h(o[d] / den);
#endif
}

// ---------------------------------------------------------------------------
extern "C" void kernel_launch(void* const* d_in, const int* in_sizes, int n_in,
                              void* d_out, int out_size) {
    const float* x      = (const float*)d_in[0];
    const float* dw_w   = (const float*)d_in[1];
    const float* qkv_w  = (const float*)d_in[2];
    const float* proj_w = (const float*)d_in[3];
    const float* proj_b = (const float*)d_in[4];
    float* out = (float*)d_out;

    u16 *pythi, *pytlo, *pwhi, *pwlo, *ppwhi, *ppwlo;
    u16 *pqkthi, *pqktlo, *pvth, *poth;
    cudaGetSymbolAddress((void**)&pythi,  g_ythi);
    cudaGetSymbolAddress((void**)&pytlo,  g_ytlo);
    cudaGetSymbolAddress((void**)&pwhi,   g_whi);
    cudaGetSymbolAddress((void**)&pwlo,   g_wlo);
    cudaGetSymbolAddress((void**)&ppwhi,  g_pwhi);
    cudaGetSymbolAddress((void**)&ppwlo,  g_pwlo);
    cudaGetSymbolAddress((void**)&pqkthi, g_qkthi);
    cudaGetSymbolAddress((void**)&pqktlo, g_qktlo);
    cudaGetSymbolAddress((void**)&pvth,   g_vth);
    cudaGetSymbolAddress((void**)&poth,   g_oth);

    cudaFuncSetAttribute(k_attn, cudaFuncAttributeMaxDynamicSharedMemorySize, ATT_SMEM);
    cudaFuncSetAttribute(k_gemm_tc, cudaFuncAttributeMaxDynamicSharedMemorySize, GM_SMEM);

    // 1) fused dwconv + transpose + split
    {
        dim3 grid(NPIX / 32, CDIM / 32, BATCH);
        k_dwt<<<grid, dim3(32, 8)>>>(x, dw_w, pythi, pytlo);
    }
    // 2) weight conversions
    k_cvt<<<(3 * CDIM * CDIM + 255) / 256, 256>>>(qkv_w, pwhi, pwlo, 3 * CDIM * CDIM);
    k_cvt<<<(CDIM * CDIM + 255) / 256, 256>>>(proj_w, ppwhi, ppwlo, CDIM * CDIM);

    long long sYT = (long long)NPIX * CDIM / 8;

    // qk GEMM
    {
        dim3 grid(NPIX / 128, QKD / 128, BATCH);
        k_gemm_tc<<<grid, 256, GM_SMEM>>>(
            (const uint4*)pythi, (const uint4*)pytlo, sYT,
            (const uint4*)pwhi, 0,
            pqkthi, pqktlo, nullptr, nullptr,
            (long long)NPIX * QKD, QKD, ATT_SCALE_L2E, 512, 2);
    }
    // V GEMM
    {
        dim3 grid(CDIM / 128, NPIX / 128, BATCH);
        k_gemm_tc<<<grid, 256, GM_SMEM>>>(
            (const uint4*)(pwhi + 1024 * CDIM), (const uint4*)(pwlo + 1024 * CDIM), 0,
            (const uint4*)pythi, sYT,
            pvth, nullptr, nullptr, nullptr,
            (long long)CDIM * NPIX, NPIX, 1.0f, 0, 1);
    }
    // attention
    {
        dim3 grid(NPIX / 128, HEADS, BATCH);
        k_attn<<<grid, 256, ATT_SMEM>>>(pqkthi, pqktlo, pvth, poth);
    }
    // proj GEMM
    {
        dim3 grid(CDIM / 128, NPIX / 128, BATCH);
        k_gemm_tc<<<grid, 256, GM_SMEM>>>(
            (const uint4*)ppwhi, (const uint4*)ppwlo, 0,
            (const uint4*)poth, sYT,
            nullptr, nullptr, out, proj_b,
            (long long)CDIM * NPIX, NPIX, 1.0f, 0, 0);
    }
}

// round 17
// speedup vs baseline: 1.5539x; 1.5539x over previous
#include <cuda_runtime.h>
#include <cuda_bf16.h>
#include <cuda_fp16.h>
#include <cstdint>

// ---------------------------------------------------------------------------
// LightweightSelfAttention  (B=2, C=512, H=W=64, heads=8, dh=64)
// All-tcgen05, fp16 data plane.
// R17: tcgen05.relinquish_alloc_permit after TMEM alloc in BOTH kernels.
//      (Missing permit release serialized CTAs per SM -> occ pinned at 1;
//      explains flat 12.3% occ across R14-R16.) GEMM = R16 single-buffer
//      occ-4 config; attention = R14 design, now actually occ 2.
// ---------------------------------------------------------------------------

#if defined(__CUDA_ARCH_FEAT_SM103_ALL) || defined(__CUDA_ARCH_FEAT_SM100_ALL)
#define HAS_TC 1
#else
#define HAS_TC 0
#endif

#define BATCH 2
#define CDIM 512
#define HEADS 8
#define DH 64
#define NPIX 4096
#define TOTAL (BATCH*CDIM*NPIX)
#define QKD 1024

typedef unsigned short u16;
typedef unsigned long long u64;

__device__ u16 g_ythi[BATCH * NPIX * CDIM];
__device__ u16 g_ytlo[BATCH * NPIX * CDIM];
__device__ u16 g_whi[3 * CDIM * CDIM];
__device__ u16 g_wlo[3 * CDIM * CDIM];
__device__ u16 g_pwhi[CDIM * CDIM];
__device__ u16 g_pwlo[CDIM * CDIM];
__device__ u16 g_qkthi[BATCH * NPIX * QKD];
__device__ u16 g_qktlo[BATCH * NPIX * QKD];
__device__ u16 g_vth[BATCH * CDIM * NPIX];
__device__ u16 g_oth[BATCH * NPIX * CDIM];

#define ATT_SCALE_L2E 0.18033688f

// ---------------- helpers --------------------------------------------------
__device__ __forceinline__ uint32_t smem_u32(const void* p) {
    uint32_t a;
    asm("{ .reg .u64 t; cvta.to.shared.u64 t, %1; cvt.u32.u64 %0, t; }"
        : "=r"(a) : "l"(p));
    return a;
}
__device__ __forceinline__ u16 f2h(float x) {
    return __half_as_ushort(__float2half_rn(x));
}
__device__ __forceinline__ float h2f(u16 u) {
    return __half2float(__ushort_as_half(u));
}
#define SWZ(o) ((o) ^ (((o) >> 3) & 0x70))

#if HAS_TC
__device__ __forceinline__ unsigned elect1() {
    unsigned p;
    asm volatile("{\n\t.reg .pred p;\n\telect.sync _|p, 0xFFFFFFFF;\n\t"
                 "selp.b32 %0, 1, 0, p;\n\t}" : "=r"(p));
    return p;
}
__device__ __forceinline__ void mma_ss(uint32_t d, u64 a, u64 b, uint32_t id, uint32_t en) {
    asm volatile("{\n\t.reg .pred p;\n\tsetp.ne.u32 p, %5, 0;\n\t"
        "tcgen05.mma.cta_group::1.kind::f16 [%0], %1, %2, %3, {%4,%4,%4,%4}, p;\n\t}"
        :: "r"(d), "l"(a), "l"(b), "r"(id), "r"(0u), "r"(en) : "memory");
}
__device__ __forceinline__ void mma_ts(uint32_t d, uint32_t a, u64 b, uint32_t id, uint32_t en) {
    asm volatile("{\n\t.reg .pred p;\n\tsetp.ne.u32 p, %5, 0;\n\t"
        "tcgen05.mma.cta_group::1.kind::f16 [%0], [%1], %2, %3, {%4,%4,%4,%4}, p;\n\t}"
        :: "r"(d), "r"(a), "l"(b), "r"(id), "r"(0u), "r"(en) : "memory");
}
__device__ __forceinline__ void tc_commit(uint32_t mbar) {
    asm volatile("tcgen05.commit.cta_group::1.mbarrier::arrive::one.shared::cluster.b64 [%0];"
                 :: "r"(mbar) : "memory");
}
__device__ __forceinline__ void mbar_init1(uint32_t mbar) {
    asm volatile("mbarrier.init.shared.b64 [%0], %1;" :: "r"(mbar), "r"(1u) : "memory");
}
__device__ __forceinline__ void mbar_wait(uint32_t mbar, uint32_t ph) {
    asm volatile("{\n\t.reg .pred P1;\n\tLAB1_%=:\n\t"
        "mbarrier.try_wait.parity.acquire.cta.shared::cta.b64 P1, [%0], %1, 0x989680;\n\t"
        "@P1 bra.uni LAB2_%=;\n\tbra.uni LAB1_%=;\n\tLAB2_%=:\n\t}"
        :: "r"(mbar), "r"(ph) : "memory");
}
#define TCF_AFTER()  asm volatile("tcgen05.fence::after_thread_sync;" ::: "memory")
#define TCF_BEFORE() asm volatile("tcgen05.fence::before_thread_sync;" ::: "memory")
#define FPROXY()     asm volatile("fence.proxy.async.shared::cta;" ::: "memory")
#define TC_WAIT_LD() asm volatile("tcgen05.wait::ld.sync.aligned;" ::: "memory")
#define TC_WAIT_ST() asm volatile("tcgen05.wait::st.sync.aligned;" ::: "memory")
#define TC_RELINQ()  asm volatile("tcgen05.relinquish_alloc_permit.cta_group::1.sync.aligned;")

#define LDX32(r, ta) \
    asm volatile("tcgen05.ld.sync.aligned.32x32b.x32.b32 " \
        "{%0, %1, %2, %3, %4, %5, %6, %7, %8, %9, %10, %11, %12, %13, %14, %15, " \
        " %16, %17, %18, %19, %20, %21, %22, %23, %24, %25, %26, %27, %28, %29, %30, %31}, [%32];" \
        : "=r"((r)[0]),  "=r"((r)[1]),  "=r"((r)[2]),  "=r"((r)[3]), \
          "=r"((r)[4]),  "=r"((r)[5]),  "=r"((r)[6]),  "=r"((r)[7]), \
          "=r"((r)[8]),  "=r"((r)[9]),  "=r"((r)[10]), "=r"((r)[11]), \
          "=r"((r)[12]), "=r"((r)[13]), "=r"((r)[14]), "=r"((r)[15]), \
          "=r"((r)[16]), "=r"((r)[17]), "=r"((r)[18]), "=r"((r)[19]), \
          "=r"((r)[20]), "=r"((r)[21]), "=r"((r)[22]), "=r"((r)[23]), \
          "=r"((r)[24]), "=r"((r)[25]), "=r"((r)[26]), "=r"((r)[27]), \
          "=r"((r)[28]), "=r"((r)[29]), "=r"((r)[30]), "=r"((r)[31]) \
        : "r"(ta))

#define STX16(ta, r) \
    asm volatile("tcgen05.st.sync.aligned.32x32b.x16.b32 [%0], " \
        "{%1, %2, %3, %4, %5, %6, %7, %8, %9, %10, %11, %12, %13, %14, %15, %16};" \
        :: "r"(ta), \
           "r"((r)[0]),  "r"((r)[1]),  "r"((r)[2]),  "r"((r)[3]), \
           "r"((r)[4]),  "r"((r)[5]),  "r"((r)[6]),  "r"((r)[7]), \
           "r"((r)[8]),  "r"((r)[9]),  "r"((r)[10]), "r"((r)[11]), \
           "r"((r)[12]), "r"((r)[13]), "r"((r)[14]), "r"((r)[15]) \
        : "memory")

#define DESC_K  ((2ull<<61)|(1ull<<46)|(64ull<<32)|(1ull<<16))
__device__ __forceinline__ u64 mkdesc(uint32_t addr) {
    return DESC_K | ((u64)(addr >> 4) & 0x3FFF);
}
#define IDESC64H   ((1u<<4)|(8u<<17)|(8u<<24))
#define IDESC128H  ((1u<<4)|(16u<<17)|(8u<<24))
#endif  // HAS_TC

// ---------------- 1) fused dwconv + transpose + fp16 split -----------------
__global__ void k_dwt(const float* __restrict__ x, const float* __restrict__ w,
                      u16* __restrict__ thi, u16* __restrict__ tlo) {
    __shared__ float t[32][33];
    int b = blockIdx.z;
    int c0 = blockIdx.y * 32, n0 = blockIdx.x * 32;
    int hh = n0 >> 6, w0 = n0 & 63;
    int tx = threadIdx.x, ty = threadIdx.y;
#pragma unroll
    for (int j = 0; j < 4; j++) {
        int c = c0 + ty + j * 8;
        const float* xb = x + ((long long)(b * CDIM + c)) * NPIX;
        const float* wc = w + c * 9;
        int ww = w0 + tx;
        float s = 0.f;
#pragma unroll
        for (int i = 0; i < 3; i++) {
            int h2 = hh + i - 1;
            if ((unsigned)h2 < 64u) {
#pragma unroll
                for (int jj = 0; jj < 3; jj++) {
                    int w2 = ww + jj - 1;
                    if ((unsigned)w2 < 64u) s += xb[h2 * 64 + w2] * wc[i * 3 + jj];
                }
            }
        }
        t[ty + j * 8][tx] = s;
    }
    __syncthreads();
    long long zt = (long long)b * NPIX * CDIM;
#pragma unroll
    for (int j = 0; j < 4; j++) {
        int n = n0 + ty + j * 8;
        float v = t[tx][ty + j * 8];
        u16 h = f2h(v);
        thi[zt + (long long)n * CDIM + c0 + tx] = h;
        tlo[zt + (long long)n * CDIM + c0 + tx] = f2h(v - h2f(h));
    }
}

// ---------------- 2) fp32 -> fp16 hi/lo (weights) --------------------------
__global__ void k_cvt(const float* __restrict__ src, u16* __restrict__ hi,
                      u16* __restrict__ lo, int n) {
    int i = blockIdx.x * blockDim.x + threadIdx.x;
    if (i >= n) return;
    float v = src[i];
    u16 h = f2h(v);
    hi[i] = h;
    lo[i] = f2h(v - h2f(h));
}

// ---------------- 4/5/7) tcgen05 GEMM: 128x128, single buffer, occ 4 -------
#define GM_TMEMPTR 0
#define GM_MBAR 8
#define GM_AHI 1024
#define GM_ALO (GM_AHI + 16384)
#define GM_B   (GM_ALO + 16384)
#define GM_SMEM (GM_B + 16384)

__global__ void __launch_bounds__(256, 4) k_gemm_tc(
    const uint4* __restrict__ Ahi, const uint4* __restrict__ Alo, long long sA,
    const uint4* __restrict__ B, long long sB,
    u16* __restrict__ Ohi, u16* __restrict__ Olo,
    float* __restrict__ Ofp, const float* __restrict__ bias,
    long long sO, int ldo, float scale_q, int qcols, int out_mode) {
#if HAS_TC
    extern __shared__ char sm[];
    uint32_t sb = smem_u32(sm);
    int tid = threadIdx.x, wid = tid >> 5;
    int mrow0 = blockIdx.x * 128;
    int brow0 = blockIdx.y * 128;
    const uint4* Ah = Ahi + blockIdx.z * sA + (long long)mrow0 * 64;
    const uint4* Al = Alo + blockIdx.z * sA + (long long)mrow0 * 64;
    const uint4* Bb = B + blockIdx.z * sB + (long long)brow0 * 64;

    if (wid == 0) {
        asm volatile("tcgen05.alloc.cta_group::1.sync.aligned.shared::cta.b32 [%0], %1;"
                     :: "r"(sb + GM_TMEMPTR), "r"(128u) : "memory");
        TC_RELINQ();   // release alloc permit -> co-resident CTAs may allocate
    }
    if (tid == 0) mbar_init1(sb + GM_MBAR);
    __syncthreads();
    uint32_t tb;
    asm volatile("ld.shared.b32 %0, [%1];" : "=r"(tb) : "r"(sb + GM_TMEMPTR));

    u64 dAhi = mkdesc(sb + GM_AHI);
    u64 dAlo = mkdesc(sb + GM_ALO);
    u64 dB   = mkdesc(sb + GM_B);

    uint32_t ph = 0;
#pragma unroll 1
    for (int kc = 0; kc < 8; kc++) {
        if (kc) { mbar_wait(sb + GM_MBAR, ph); ph ^= 1; }
        int k8 = kc * 8;
#pragma unroll
        for (int l = 0; l < 4; l++) {
            int idx = tid + l * 256;
            int r = idx >> 3, j = idx & 7;
            uint32_t off = SWZ((uint32_t)(r * 128 + j * 16));
            *(uint4*)(sm + GM_AHI + off) = Ah[r * 64 + k8 + j];
            *(uint4*)(sm + GM_ALO + off) = Al[r * 64 + k8 + j];
            *(uint4*)(sm + GM_B + off)   = Bb[r * 64 + k8 + j];
        }
        FPROXY();
        __syncthreads();
        if (wid == 0) {
            if (elect1()) {
#pragma unroll
                for (int ks = 0; ks < 4; ks++)
                    mma_ss(tb, dAhi + ks * 2, dB + ks * 2, IDESC128H, !(kc == 0 && ks == 0));
#pragma unroll
                for (int ks = 0; ks < 4; ks++)
                    mma_ss(tb, dAlo + ks * 2, dB + ks * 2, IDESC128H, 1u);
                tc_commit(sb + GM_MBAR);
            }
        }
    }
    mbar_wait(sb + GM_MBAR, ph); ph ^= 1;

    if (tid < 128) {
        TCF_AFTER();
        int m = mrow0 + tid;
        long long obase0 = blockIdx.z * sO + (long long)m * ldo + brow0;
#pragma unroll 1
        for (int ch = 0; ch < 4; ch++) {
            uint32_t d[32];
            LDX32(d, tb + ch * 32);
            TC_WAIT_LD();
            long long obase = obase0 + ch * 32;
            if (Ofp) {
                float bv = bias ? bias[m] : 0.f;
#pragma unroll
                for (int j = 0; j < 8; j++) {
                    float4 v = make_float4(__uint_as_float(d[4 * j]) + bv,
                                           __uint_as_float(d[4 * j + 1]) + bv,
                                           __uint_as_float(d[4 * j + 2]) + bv,
                                           __uint_as_float(d[4 * j + 3]) + bv);
                    *(float4*)(Ofp + obase + 4 * j) = v;
                }
            } else if (out_mode == 2 && brow0 < qcols) {
                uint32_t whi[16], wlo[16];
#pragma unroll
                for (int j = 0; j < 16; j++) {
                    float a = __uint_as_float(d[2 * j]) * scale_q;
                    float c = __uint_as_float(d[2 * j + 1]) * scale_q;
                    u16 ah = f2h(a), chh = f2h(c);
                    whi[j] = (uint32_t)ah | ((uint32_t)chh << 16);
                    u16 al = f2h(a - h2f(ah)), cl = f2h(c - h2f(chh));
                    wlo[j] = (uint32_t)al | ((uint32_t)cl << 16);
                }
#pragma unroll
                for (int j = 0; j < 4; j++) {
                    *(uint4*)(Ohi + obase + 8 * j) = *(uint4*)&whi[4 * j];
                    *(uint4*)(Olo + obase + 8 * j) = *(uint4*)&wlo[4 * j];
                }
            } else {
                uint32_t w[16];
#pragma unroll
                for (int j = 0; j < 16; j++) {
                    u16 a = f2h(__uint_as_float(d[2 * j]));
                    u16 c = f2h(__uint_as_float(d[2 * j + 1]));
                    w[j] = (uint32_t)a | ((uint32_t)c << 16);
                }
#pragma unroll
                for (int j = 0; j < 4; j++)
                    *(uint4*)(Ohi + obase + 8 * j) = *(uint4*)&w[4 * j];
            }
        }
    }
    __syncthreads();
    if (wid == 0) {
        asm volatile("tcgen05.dealloc.cta_group::1.sync.aligned.b32 %0, %1;"
                     :: "r"(tb), "r"(128u));
    }
#else
    // compile-only fallback
    int tid = threadIdx.x;
    const u16* Ah = (const u16*)(Ahi + blockIdx.z * sA) + (long long)blockIdx.x * 128 * 512;
    const u16* Al = (const u16*)(Alo + blockIdx.z * sA) + (long long)blockIdx.x * 128 * 512;
    const u16* Bb = (const u16*)(B + blockIdx.z * sB) + (long long)blockIdx.y * 128 * 512;
    for (int e = tid; e < 128 * 128; e += 256) {
        int r = e >> 7, j = e & 127;
        float s = 0.f;
        for (int k = 0; k < 512; k++)
            s += (h2f(Ah[r * 512 + k]) + h2f(Al[r * 512 + k])) * h2f(Bb[j * 512 + k]);
        int m = blockIdx.x * 128 + r;
        long long obase = blockIdx.z * sO + (long long)m * ldo + blockIdx.y * 128 + j;
        if (Ofp) {
            Ofp[obase] = s + (bias ? bias[m] : 0.f);
        } else if (out_mode == 2 && blockIdx.y * 128 < qcols) {
            s *= scale_q;
            u16 hh = f2h(s);
            Ohi[obase] = hh;
            Olo[obase] = f2h(s - h2f(hh));
        } else {
            Ohi[obase] = f2h(s);
        }
    }
#endif
}

// ---------------- 6) attention (R14 + permit release) ----------------------
#define SM_TMEMPTR 0
#define SM_MBAR 8
#define SM_DEN 1024
#define SM_QHI 2048
#define SM_QLO (SM_QHI + 16384)
#define SM_KH(b) (34816 + (b) * 8192)
#define SM_VH(b) (51200 + (b) * 8192)
#define ATT_SMEM 67584

#define TM_S(b) ((b) * 64)
#define TM_O 128
#define TM_PH 192
#define ATT_TMCOLS 256

__global__ void __launch_bounds__(256) k_attn(
    const u16* __restrict__ qkthi, const u16* __restrict__ qktlo,
    const u16* __restrict__ vth, u16* __restrict__ oth) {
#if HAS_TC
    extern __shared__ char sm[];
    uint32_t sb = smem_u32(sm);
    int tid = threadIdx.x, wid = tid >> 5;
    int half = wid >> 2;
    uint32_t lofs = (uint32_t)(wid & 3) << 21;
    int n0 = blockIdx.x * 128;
    int h = blockIdx.y, b = blockIdx.z;
    const uint4* qh4 = (const uint4*)qkthi + (long long)b * NPIX * 128;
    const uint4* ql4 = (const uint4*)qktlo + (long long)b * NPIX * 128;
    const uint4* vh4 = (const uint4*)vth + ((long long)b * CDIM + h * DH) * 512;

    if (wid == 0) {
        asm volatile("tcgen05.alloc.cta_group::1.sync.aligned.shared::cta.b32 [%0], %1;"
                     :: "r"(sb + SM_TMEMPTR), "r"((uint32_t)ATT_TMCOLS) : "memory");
        TC_RELINQ();   // release alloc permit -> second CTA can allocate
    }
    if (tid == 0) mbar_init1(sb + SM_MBAR);
    __syncthreads();
    uint32_t tb;
    asm volatile("ld.shared.b32 %0, [%1];" : "=r"(tb) : "r"(sb + SM_TMEMPTR));

    int r0a = tid >> 3, ja = tid & 7;
    int r0b = (tid + 256) >> 3, jb = (tid + 256) & 7;
    uint32_t offa = SWZ((uint32_t)(r0a * 128 + ja * 16));
    uint32_t offb = SWZ((uint32_t)(r0b * 128 + jb * 16));

#pragma unroll
    for (int l = 0; l < 4; l++) {
        int idx = tid + l * 256;
        int r = idx >> 3, j = idx & 7;
        uint32_t off = SWZ((uint32_t)(r * 128 + j * 16));
        *(uint4*)(sm + SM_QHI + off) = qh4[(long long)(n0 + r) * 128 + h * 8 + j];
        *(uint4*)(sm + SM_QLO + off) = ql4[(long long)(n0 + r) * 128 + h * 8 + j];
    }
#pragma unroll
    for (int l = 0; l < 2; l++) {
        int idx = tid + l * 256;
        int r = idx >> 3, j = idx & 7;
        uint32_t off = SWZ((uint32_t)(r * 128 + j * 16));
        *(uint4*)(sm + SM_KH(0) + off) = qh4[(long long)r * 128 + 64 + h * 8 + j];
        *(uint4*)(sm + SM_KH(1) + off) = qh4[(long long)(64 + r) * 128 + 64 + h * 8 + j];
        *(uint4*)(sm + SM_VH(0) + off) = vh4[(long long)r * 512 + j];
    }
    FPROXY();
    __syncthreads();

    u64 aQhi = mkdesc(sb + SM_QHI);
    u64 aQlo = mkdesc(sb + SM_QLO);

    if (wid == 0) {
        if (elect1()) {
            u64 dK = mkdesc(sb + SM_KH(0));
#pragma unroll
            for (int ks = 0; ks < 4; ks++)
                mma_ss(tb + TM_S(0), aQhi + ks * 2, dK + ks * 2, IDESC64H, ks > 0);
#pragma unroll
            for (int ks = 0; ks < 4; ks++)
                mma_ss(tb + TM_S(0), aQlo + ks * 2, dK + ks * 2, IDESC64H, 1u);
            tc_commit(sb + SM_MBAR);
        }
    }

    float den = 0.f;
    uint32_t ph = 0;

#pragma unroll 1
    for (int t = 0; t < 64; t++) {
        mbar_wait(sb + SM_MBAR, ph); ph ^= 1;
        TCF_AFTER();

        if (t < 63 && wid == 0) {
            if (elect1()) {
                int nb = (t + 1) & 1;
                u64 dK = mkdesc(sb + SM_KH(nb));
#pragma unroll
                for (int ks = 0; ks < 4; ks++)
                    mma_ss(tb + TM_S(nb), aQhi + ks * 2, dK + ks * 2, IDESC64H, ks > 0);
#pragma unroll
                for (int ks = 0; ks < 4; ks++)
                    mma_ss(tb + TM_S(nb), aQlo + ks * 2, dK + ks * 2, IDESC64H, 1u);
            }
        }

        uint4 kra, krb, vra, vrb;
        bool hask = (t <= 61), hasv = (t <= 62);
        if (hask) {
            int m2 = (t + 2) * 64;
            kra = qh4[(long long)(m2 + r0a) * 128 + 64 + h * 8 + ja];
            krb = qh4[(long long)(m2 + r0b) * 128 + 64 + h * 8 + jb];
        }
        if (hasv) {
            int m1 = (t + 1) * 8;
            vra = vh4[(long long)r0a * 512 + m1 + ja];
            vrb = vh4[(long long)r0b * 512 + m1 + jb];
        }

        {
            uint32_t sr[32];
            LDX32(sr, tb + TM_S(t & 1) + half * 32);
            TC_WAIT_LD();
            uint32_t w[16];
            float dsum = 0.f;
#pragma unroll
            for (int j = 0; j < 16; j++) {
                uint32_t s2, p2;
                asm("cvt.rn.f16x2.f32 %0, %1, %2;" : "=r"(s2)
                    : "f"(__uint_as_float(sr[2 * j + 1])), "f"(__uint_as_float(sr[2 * j])));
                asm("ex2.approx.f16x2 %0, %1;" : "=r"(p2) : "r"(s2));
                w[j] = p2;
                dsum += h2f((u16)(p2 & 0xFFFF)) + h2f((u16)(p2 >> 16));
            }
            den += dsum;
            STX16(tb + TM_PH + half * 16 + lofs, w);
            TC_WAIT_ST();
        }

        if (hask) {
            *(uint4*)(sm + SM_KH(t & 1) + offa) = kra;
            *(uint4*)(sm + SM_KH(t & 1) + offb) = krb;
        }
        if (hasv) {
            *(uint4*)(sm + SM_VH((t + 1) & 1) + offa) = vra;
            *(uint4*)(sm + SM_VH((t + 1) & 1) + offb) = vrb;
        }
        TCF_BEFORE();
        FPROXY();
        __syncthreads();

        if (wid == 0) {
            if (elect1()) {
                TCF_AFTER();
                u64 dVh = mkdesc(sb + SM_VH(t & 1));
#pragma unroll
                for (int ks = 0; ks < 4; ks++)
                    mma_ts(tb + TM_O, tb + TM_PH + ks * 8, dVh + ks * 2, IDESC64H,
                           (t > 0 || ks > 0) ? 1u : 0u);
                tc_commit(sb + SM_MBAR);
            }
        }
    }
    mbar_wait(sb + SM_MBAR, ph); ph ^= 1;

    *(float*)(sm + SM_DEN + tid * 4) = den;
    __syncthreads();

    if (tid < 128) {
        TCF_AFTER();
        uint32_t orr[64];
        LDX32(orr, tb + TM_O);
        LDX32(orr + 32, tb + TM_O + 32);
        TC_WAIT_LD();
        float dtot = *(float*)(sm + SM_DEN + tid * 4) +
                     *(float*)(sm + SM_DEN + (tid + 128) * 4);
        float inv = 1.0f / dtot;
        long long obase = ((long long)b * NPIX + n0 + tid) * CDIM + h * DH;
        uint32_t w[32];
#pragma unroll
        for (int j = 0; j < 32; j++) {
            u16 a = f2h(__uint_as_float(orr[2 * j]) * inv);
            u16 c = f2h(__uint_as_float(orr[2 * j + 1]) * inv);
            w[j] = (uint32_t)a | ((uint32_t)c << 16);
        }
#pragma unroll
        for (int j = 0; j < 8; j++)
            *(uint4*)(oth + obase + 8 * j) = *(uint4*)&w[4 * j];
    }
    __syncthreads();
    if (wid == 0) {
        asm volatile("tcgen05.dealloc.cta_group::1.sync.aligned.b32 %0, %1;"
                     :: "r"(tb), "r"((uint32_t)ATT_TMCOLS));
    }
#else
    // compile-only fallback
    int tid = threadIdx.x;
    if (tid >= 128) return;
    int n0 = blockIdx.x * 128;
    int h = blockIdx.y, b = blockIdx.z;
    long long qb = (long long)b * NPIX * QKD;
    int r = n0 + tid;
    float q[64], o[64], den = 0.f;
#pragma unroll
    for (int d = 0; d < 64; d++) {
        q[d] = h2f(qkthi[qb + (long long)r * QKD + h * 64 + d]) +
               h2f(qktlo[qb + (long long)r * QKD + h * 64 + d]);
        o[d] = 0.f;
    }
    for (int key = 0; key < NPIX; key++) {
        float s = 0.f;
        for (int d = 0; d < 64; d++)
            s += q[d] * h2f(qkthi[qb + (long long)key * QKD + 512 + h * 64 + d]);
        float p = h2f(f2h(exp2f(h2f(f2h(s)))));
        den += p;
        for (int d = 0; d < 64; d++) {
            long long vi = ((long long)b * CDIM + h * 64 + d) * NPIX + key;
            o[d] += p * h2f(vth[vi]);
        }
    }
    long long ob = ((long long)b * NPIX + r) * CDIM + h * 64;
    for (int d = 0; d < 64; d++) oth[ob + d] = f2h(o[d] / den);
#endif
}

// ---------------------------------------------------------------------------
extern "C" void kernel_launch(void* const* d_in, const int* in_sizes, int n_in,
                              void* d_out, int out_size) {
    const float* x      = (const float*)d_in[0];
    const float* dw_w   = (const float*)d_in[1];
    const float* qkv_w  = (const float*)d_in[2];
    const float* proj_w = (const float*)d_in[3];
    const float* proj_b = (const float*)d_in[4];
    float* out = (float*)d_out;

    u16 *pythi, *pytlo, *pwhi, *pwlo, *ppwhi, *ppwlo;
    u16 *pqkthi, *pqktlo, *pvth, *poth;
    cudaGetSymbolAddress((void**)&pythi,  g_ythi);
    cudaGetSymbolAddress((void**)&pytlo,  g_ytlo);
    cudaGetSymbolAddress((void**)&pwhi,   g_whi);
    cudaGetSymbolAddress((void**)&pwlo,   g_wlo);
    cudaGetSymbolAddress((void**)&ppwhi,  g_pwhi);
    cudaGetSymbolAddress((void**)&ppwlo,  g_pwlo);
    cudaGetSymbolAddress((void**)&pqkthi, g_qkthi);
    cudaGetSymbolAddress((void**)&pqktlo, g_qktlo);
    cudaGetSymbolAddress((void**)&pvth,   g_vth);
    cudaGetSymbolAddress((void**)&poth,   g_oth);

    cudaFuncSetAttribute(k_attn, cudaFuncAttributeMaxDynamicSharedMemorySize, ATT_SMEM);
    cudaFuncSetAttribute(k_gemm_tc, cudaFuncAttributeMaxDynamicSharedMemorySize, GM_SMEM);

    // 1) fused dwconv + transpose + split
    {
        dim3 grid(NPIX / 32, CDIM / 32, BATCH);
        k_dwt<<<grid, dim3(32, 8)>>>(x, dw_w, pythi, pytlo);
    }
    // 2) weight conversions
    k_cvt<<<(3 * CDIM * CDIM + 255) / 256, 256>>>(qkv_w, pwhi, pwlo, 3 * CDIM * CDIM);
    k_cvt<<<(CDIM * CDIM + 255) / 256, 256>>>(proj_w, ppwhi, ppwlo, CDIM * CDIM);

    long long sYT = (long long)NPIX * CDIM / 8;

    // qk GEMM
    {
        dim3 grid(NPIX / 128, QKD / 128, BATCH);
        k_gemm_tc<<<grid, 256, GM_SMEM>>>(
            (const uint4*)pythi, (const uint4*)pytlo, sYT,
            (const uint4*)pwhi, 0,
            pqkthi, pqktlo, nullptr, nullptr,
            (long long)NPIX * QKD, QKD, ATT_SCALE_L2E, 512, 2);
    }
    // V GEMM
    {
        dim3 grid(CDIM / 128, NPIX / 128, BATCH);
        k_gemm_tc<<<grid, 256, GM_SMEM>>>(
            (const uint4*)(pwhi + 1024 * CDIM), (const uint4*)(pwlo + 1024 * CDIM), 0,
            (const uint4*)pythi, sYT,
            pvth, nullptr, nullptr, nullptr,
            (long long)CDIM * NPIX, NPIX, 1.0f, 0, 1);
    }
    // attention
    {
        dim3 grid(NPIX / 128, HEADS, BATCH);
        k_attn<<<grid, 256, ATT_SMEM>>>(pqkthi, pqktlo, pvth, poth);
    }
    // proj GEMM
    {
        dim3 grid(CDIM / 128, NPIX / 128, BATCH);
        k_gemm_tc<<<grid, 256, GM_SMEM>>>(
            (const uint4*)ppwhi, (const uint4*)ppwlo, 0,
            (const uint4*)poth, sYT,
            nullptr, nullptr, out, proj_b,
            (long long)CDIM * NPIX, NPIX, 1.0f, 0, 0);
    }
}